// round 4
// baseline (speedup 1.0000x reference)
#include <cuda_runtime.h>
#include <math.h>

#define NN 100000
#define EE 1600000
#define ET 1700000          // EE + NN self loops
#define EDIM 8
#define HH 4
#define NEG 0.2f
#define EPSV 1e-16f

// ---------------- static device scratch (no allocations allowed) ----------------
__device__ __align__(16) int      g_src[ET];
__device__ __align__(16) int      g_dst[ET];
__device__ __align__(16) float    g_alpha[ET * HH];     // alpha, then overwritten with exp()
__device__ __align__(16) float    g_h[NN * 128];        // per-node head features (max HC=128)
__device__ __align__(16) float    g_acc[NN * 128];      // aggregation accumulator
__device__ __align__(16) float    g_x2[NN * 32];        // layer-2 input
__device__ __align__(16) float    g_as[NN * HH];
__device__ __align__(16) float    g_ad[NN * HH];
__device__ __align__(16) unsigned g_amax[NN * HH];      // order-encoded float max
__device__ __align__(16) float    g_denom[NN * HH];     // softmax denom, then its reciprocal
__device__             float      g_ve[HH * EDIM];      // folded edge-attr attention vector
__device__             unsigned   g_odd_or;             // edge_index dtype detection

// order-preserving float<->uint encoding for atomicMax
__device__ __forceinline__ unsigned flipf(float f) {
    unsigned u = __float_as_uint(f);
    return (u & 0x80000000u) ? ~u : (u | 0x80000000u);
}
__device__ __forceinline__ float unflipf(unsigned u) {
    return __uint_as_float((u & 0x80000000u) ? (u & 0x7FFFFFFFu) : ~u);
}

// ---------------- dtype detection for edge_index (int32 vs int64) ----------------
// If the buffer holds int64 values in [0, 2^31), every odd 32-bit word is 0.
// If it holds int32 (JAX x64-disabled demotes jnp.int64 -> int32), odd words are
// real random indices and their OR is nonzero with overwhelming probability.
__global__ void detect_init_kernel() { g_odd_or = 0u; }

__global__ void detect_kernel(const unsigned* __restrict__ w) {
    int i = blockIdx.x * blockDim.x + threadIdx.x;
    unsigned acc = 0u;
    if (i < EE) acc = w[2 * (size_t)i + 1];   // odd words of first EE elements
    #pragma unroll
    for (int off = 16; off > 0; off >>= 1)
        acc |= __shfl_xor_sync(0xffffffffu, acc, off);
    if ((threadIdx.x & 31) == 0 && acc) atomicOr(&g_odd_or, acc);
}

// edge index -> int32 src/dst (dtype chosen by detection), append self loops
__global__ void prep_edges_kernel(const void* __restrict__ eiv) {
    int e = blockIdx.x * blockDim.x + threadIdx.x;
    if (e >= ET) return;
    if (e < EE) {
        int s, d;
        if (g_odd_or != 0u) {                  // int32 layout
            const int* p = (const int*)eiv;
            s = p[e];
            d = p[(size_t)EE + e];
        } else {                               // int64 layout
            const long long* p = (const long long*)eiv;
            s = (int)p[e];
            d = (int)p[(size_t)EE + e];
        }
        // defensive clamp: wrong index -> wrong answer (visible), not IMA
        s = s < 0 ? 0 : (s >= NN ? NN - 1 : s);
        d = d < 0 ? 0 : (d >= NN ? NN - 1 : d);
        g_src[e] = s;
        g_dst[e] = d;
    } else {
        int n = e - EE;
        g_src[e] = n;
        g_dst[e] = n;
    }
}

// ve[h*8+d] = sum_c We[d, h*C+c] * a_edge[h, c]
template <int HC, int C>
__global__ void compute_ve_kernel(const float* __restrict__ We,
                                  const float* __restrict__ a_edge) {
    int t = threadIdx.x;
    if (t < HH * EDIM) {
        int h = t / EDIM, d = t % EDIM;
        float s = 0.f;
        #pragma unroll
        for (int c = 0; c < C; c++) s += We[d * HC + h * C + c] * a_edge[h * C + c];
        g_ve[h * EDIM + d] = s;
    }
}

// h = x @ W  (fused with a_src / a_dst per-head dots)
template <int FIN, int HC, int C>
__global__ void gemm_att_kernel(const float* __restrict__ x,
                                const float* __restrict__ W,
                                const float* __restrict__ a_src,
                                const float* __restrict__ a_dst) {
    constexpr int ROWS = 32;
    __shared__ float Ws[FIN * HC];
    __shared__ float xs[ROWS * FIN];
    __shared__ float asv[HC], adv[HC];
    int t = threadIdx.x;                       // blockDim.x == HC
    for (int i = t; i < FIN * HC; i += HC) Ws[i] = W[i];
    asv[t] = a_src[t];
    adv[t] = a_dst[t];
    int n0 = blockIdx.x * ROWS;
    for (int i = t; i < ROWS * FIN; i += HC) {
        int r = i / FIN, f = i % FIN;
        int n = n0 + r;
        xs[i] = (n < NN) ? x[(size_t)n * FIN + f] : 0.0f;
    }
    __syncthreads();

    for (int r = 0; r < ROWS; r += 4) {
        float acc[4] = {0.f, 0.f, 0.f, 0.f};
        #pragma unroll
        for (int f = 0; f < FIN; f++) {
            float w = Ws[f * HC + t];
            acc[0] += xs[(r + 0) * FIN + f] * w;
            acc[1] += xs[(r + 1) * FIN + f] * w;
            acc[2] += xs[(r + 2) * FIN + f] * w;
            acc[3] += xs[(r + 3) * FIN + f] * w;
        }
        #pragma unroll
        for (int j = 0; j < 4; j++) {
            int n = n0 + r + j;
            if (n < NN) g_h[(size_t)n * HC + t] = acc[j];
            float ps = acc[j] * asv[t];
            float pd = acc[j] * adv[t];
            #pragma unroll
            for (int off = C / 2; off > 0; off >>= 1) {
                ps += __shfl_xor_sync(0xffffffffu, ps, off);
                pd += __shfl_xor_sync(0xffffffffu, pd, off);
            }
            if ((t % C) == 0 && n < NN) {
                int head = t / C;
                g_as[n * HH + head] = ps;
                g_ad[n * HH + head] = pd;
            }
        }
    }
}

__global__ void zero_kernel() {
    int i = blockIdx.x * blockDim.x + threadIdx.x;
    if (i < NN * 128) g_acc[i] = 0.0f;
    if (i < NN * HH) { g_amax[i] = 0u; g_denom[i] = 0.0f; }
}

// alpha = leaky(as[src] + ad[dst] + ae); segment max via atomicMax
__global__ void edge_alpha_kernel(const float* __restrict__ edge_attr) {
    __shared__ float ves[HH * EDIM];
    if (threadIdx.x < HH * EDIM) ves[threadIdx.x] = g_ve[threadIdx.x];
    __syncthreads();
    int e = blockIdx.x * blockDim.x + threadIdx.x;
    if (e >= ET) return;
    int s = g_src[e], d = g_dst[e];
    float4 as4 = *(const float4*)&g_as[s * HH];
    float4 ad4 = *(const float4*)&g_ad[d * HH];
    float ae[HH] = {0.f, 0.f, 0.f, 0.f};
    if (e < EE) {
        float4 ea0 = __ldg((const float4*)(edge_attr + (size_t)e * EDIM));
        float4 ea1 = __ldg((const float4*)(edge_attr + (size_t)e * EDIM + 4));
        float eav[8] = {ea0.x, ea0.y, ea0.z, ea0.w, ea1.x, ea1.y, ea1.z, ea1.w};
        #pragma unroll
        for (int h = 0; h < HH; h++) {
            float acc = 0.f;
            #pragma unroll
            for (int k = 0; k < EDIM; k++) acc += eav[k] * ves[h * EDIM + k];
            ae[h] = acc;
        }
    }
    float a0 = as4.x + ad4.x + ae[0]; a0 = a0 > 0.f ? a0 : NEG * a0;
    float a1 = as4.y + ad4.y + ae[1]; a1 = a1 > 0.f ? a1 : NEG * a1;
    float a2 = as4.z + ad4.z + ae[2]; a2 = a2 > 0.f ? a2 : NEG * a2;
    float a3 = as4.w + ad4.w + ae[3]; a3 = a3 > 0.f ? a3 : NEG * a3;
    *(float4*)&g_alpha[(size_t)e * HH] = make_float4(a0, a1, a2, a3);
    atomicMax(&g_amax[d * HH + 0], flipf(a0));
    atomicMax(&g_amax[d * HH + 1], flipf(a1));
    atomicMax(&g_amax[d * HH + 2], flipf(a2));
    atomicMax(&g_amax[d * HH + 3], flipf(a3));
}

// ex = exp(alpha - amax[dst]); segment sum via vector red
__global__ void edge_exp_kernel() {
    int e = blockIdx.x * blockDim.x + threadIdx.x;
    if (e >= ET) return;
    int d = g_dst[e];
    float4 a4 = *(const float4*)&g_alpha[(size_t)e * HH];
    uint4 m4 = *(const uint4*)&g_amax[d * HH];
    float4 ex;
    ex.x = __expf(a4.x - unflipf(m4.x));
    ex.y = __expf(a4.y - unflipf(m4.y));
    ex.z = __expf(a4.z - unflipf(m4.z));
    ex.w = __expf(a4.w - unflipf(m4.w));
    *(float4*)&g_alpha[(size_t)e * HH] = ex;
    atomicAdd((float4*)&g_denom[d * HH], ex);
}

// denom -> 1/(denom + eps)  (hoists MUFU out of the hot aggregation pass)
__global__ void denom_rcp_kernel() {
    int i = blockIdx.x * blockDim.x + threadIdx.x;
    if (i < NN * HH) g_denom[i] = 1.0f / (g_denom[i] + EPSV);
}

// out[dst] += w * h[src], warp(-fraction) per edge, float4 vector reductions
template <int HC>
__global__ void edge_agg_kernel() {
    constexpr int C = HC / HH;
    constexpr int LPE = HC / 4;        // lanes per edge (float4 each)
    constexpr int EPW = 32 / LPE;      // edges per warp
    int gwarp = (blockIdx.x * blockDim.x + threadIdx.x) >> 5;
    int lane = threadIdx.x & 31;
    int e = gwarp * EPW + lane / LPE;
    if (e >= ET) return;
    int l = lane % LPE;
    int s = g_src[e], d = g_dst[e];
    float4 ex4 = *(const float4*)&g_alpha[(size_t)e * HH];
    float4 rd4 = *(const float4*)&g_denom[d * HH];
    float w[HH] = {ex4.x * rd4.x, ex4.y * rd4.y, ex4.z * rd4.z, ex4.w * rd4.w};
    int col = l * 4;
    float wh = w[col / C];
    float4 hv = *(const float4*)&g_h[(size_t)s * HC + col];
    float4 cv = make_float4(hv.x * wh, hv.y * wh, hv.z * wh, hv.w * wh);
    atomicAdd((float4*)&g_acc[(size_t)d * HC + col], cv);
}

// mean over heads + bias + ELU
template <int HC, int C>
__global__ void finalize_kernel(const float* __restrict__ b, float* __restrict__ out) {
    int i = blockIdx.x * blockDim.x + threadIdx.x;
    if (i >= NN * C) return;
    int n = i / C, c = i % C;
    float sum = 0.f;
    #pragma unroll
    for (int h = 0; h < HH; h++) sum += g_acc[(size_t)n * HC + h * C + c];
    float v = 0.25f * sum + b[c];
    out[i] = v > 0.f ? v : expm1f(v);
}

// ---------------- launch ----------------
extern "C" void kernel_launch(void* const* d_in, const int* in_sizes, int n_in,
                              void* d_out, int out_size) {
    const float* x   = (const float*)d_in[0];
    const void*  ei  = d_in[1];                   // int32 or int64 — detected on device
    const float* ea  = (const float*)d_in[2];
    const float* W1  = (const float*)d_in[3];
    const float* We1 = (const float*)d_in[4];
    const float* as1 = (const float*)d_in[5];
    const float* ad1 = (const float*)d_in[6];
    const float* ae1 = (const float*)d_in[7];
    const float* b1  = (const float*)d_in[8];
    const float* W2  = (const float*)d_in[9];
    const float* We2 = (const float*)d_in[10];
    const float* as2 = (const float*)d_in[11];
    const float* ad2 = (const float*)d_in[12];
    const float* ae2 = (const float*)d_in[13];
    const float* b2  = (const float*)d_in[14];
    float* out = (float*)d_out;

    float* x2p = nullptr;
    cudaGetSymbolAddress((void**)&x2p, g_x2);

    const int TB = 256;

    detect_init_kernel<<<1, 1>>>();
    detect_kernel<<<(EE + TB - 1) / TB, TB>>>((const unsigned*)ei);
    prep_edges_kernel<<<(ET + TB - 1) / TB, TB>>>(ei);

    // ---- layer 1: Fin=64, HC=128, C=32 ----
    compute_ve_kernel<128, 32><<<1, 32>>>(We1, ae1);
    gemm_att_kernel<64, 128, 32><<<(NN + 31) / 32, 128>>>(x, W1, as1, ad1);
    zero_kernel<<<(NN * 128 + TB - 1) / TB, TB>>>();
    edge_alpha_kernel<<<(ET + TB - 1) / TB, TB>>>(ea);
    edge_exp_kernel<<<(ET + TB - 1) / TB, TB>>>();
    denom_rcp_kernel<<<(NN * HH + TB - 1) / TB, TB>>>();
    edge_agg_kernel<128><<<(ET + 7) / 8, TB>>>();            // 8 edges / 256-thr block
    finalize_kernel<128, 32><<<(NN * 32 + TB - 1) / TB, TB>>>(b1, x2p);

    // ---- layer 2: Fin=32, HC=64, C=16 ----
    compute_ve_kernel<64, 16><<<1, 32>>>(We2, ae2);
    gemm_att_kernel<32, 64, 16><<<(NN + 31) / 32, 64>>>(x2p, W2, as2, ad2);
    zero_kernel<<<(NN * 128 + TB - 1) / TB, TB>>>();
    edge_alpha_kernel<<<(ET + TB - 1) / TB, TB>>>(ea);
    edge_exp_kernel<<<(ET + TB - 1) / TB, TB>>>();
    denom_rcp_kernel<<<(NN * HH + TB - 1) / TB, TB>>>();
    edge_agg_kernel<64><<<(ET + 15) / 16, TB>>>();           // 16 edges / block
    finalize_kernel<64, 16><<<(NN * 16 + TB - 1) / TB, TB>>>(b2, out);
}

// round 7
// speedup vs baseline: 1.6600x; 1.6600x over previous
#include <cuda_runtime.h>
#include <math.h>

#define NN 100000
#define EE 1600000
#define ET 1700000          // EE + NN self loops
#define EDIM 8
#define HH 4
#define NEG 0.2f
#define EPSV 1e-16f
#define SCAN_BLK 1024
#define NBLK ((NN + SCAN_BLK - 1) / SCAN_BLK)   // 98

// ---------------- static device scratch ----------------
__device__ int      g_src[ET];
__device__ int      g_dst[ET];
__device__ int      g_deg[NN];
__device__ int      g_row[NN + 1];
__device__ int      g_woff[NN];
__device__ int      g_bsum[NBLK];
__device__ int      g_bscan[NBLK];
__device__ int      g_csrc[ET];                 // CSR: src per slot
__device__ __align__(16) float g_ae1[ET * HH];  // CSR-ordered edge attention, layer 1
__device__ __align__(16) float g_ae2[ET * HH];  // CSR-ordered edge attention, layer 2
__device__ __align__(16) float g_exp[ET * HH];  // CSR-ordered exp(alpha), per layer
__device__ __align__(16) float g_h[NN * 128];   // per-node head features (max HC=128)
__device__ __align__(16) float g_x2[NN * 32];   // layer-2 input
__device__ __align__(16) float g_as[NN * HH];
__device__ __align__(16) float g_ad[NN * HH];
__device__ float    g_ve1[HH * EDIM];
__device__ float    g_ve2[HH * EDIM];
__device__ unsigned g_odd_or;

// ---------------- dtype detection for edge_index (int32 vs int64) ----------------
__global__ void detect_init_kernel() { g_odd_or = 0u; }

__global__ void detect_kernel(const unsigned* __restrict__ w) {
    int i = blockIdx.x * blockDim.x + threadIdx.x;
    unsigned acc = 0u;
    if (i < EE) acc = w[2 * (size_t)i + 1];
    #pragma unroll
    for (int off = 16; off > 0; off >>= 1)
        acc |= __shfl_xor_sync(0xffffffffu, acc, off);
    if ((threadIdx.x & 31) == 0 && acc) atomicOr(&g_odd_or, acc);
}

__global__ void zero_deg_kernel() {
    int i = blockIdx.x * blockDim.x + threadIdx.x;
    if (i < NN) g_deg[i] = 0;
}

// decode edges (+ self loops), clamp, histogram of dst
__global__ void prep_edges_kernel(const void* __restrict__ eiv) {
    int e = blockIdx.x * blockDim.x + threadIdx.x;
    if (e >= ET) return;
    int s, d;
    if (e < EE) {
        if (g_odd_or != 0u) {                  // int32 layout
            const int* p = (const int*)eiv;
            s = p[e];
            d = p[(size_t)EE + e];
        } else {                               // int64 layout
            const long long* p = (const long long*)eiv;
            s = (int)p[e];
            d = (int)p[(size_t)EE + e];
        }
        s = s < 0 ? 0 : (s >= NN ? NN - 1 : s);
        d = d < 0 ? 0 : (d >= NN ? NN - 1 : d);
    } else {
        s = d = e - EE;
    }
    g_src[e] = s;
    g_dst[e] = d;
    atomicAdd(&g_deg[d], 1);
}

// ---------------- exclusive scan of g_deg -> g_row ----------------
__global__ void scan_a_kernel() {
    __shared__ int part[256];
    int b = blockIdx.x, t = threadIdx.x;
    int base = b * SCAN_BLK + t * 4;
    int v[4];
    #pragma unroll
    for (int j = 0; j < 4; j++) v[j] = (base + j < NN) ? g_deg[base + j] : 0;
    int tsum = v[0] + v[1] + v[2] + v[3];
    part[t] = tsum;
    __syncthreads();
    for (int off = 1; off < 256; off <<= 1) {
        int x = (t >= off) ? part[t - off] : 0;
        __syncthreads();
        part[t] += x;
        __syncthreads();
    }
    if (t == 255) g_bsum[b] = part[255];
    int run = part[t] - tsum;       // exclusive prefix for this thread's chunk
    #pragma unroll
    for (int j = 0; j < 4; j++) {
        if (base + j < NN) g_row[base + j] = run;
        run += v[j];
    }
}

__global__ void scan_b_kernel() {
    __shared__ int sb[128];
    int t = threadIdx.x;
    int v = (t < NBLK) ? g_bsum[t] : 0;
    sb[t] = v;
    __syncthreads();
    for (int off = 1; off < 128; off <<= 1) {
        int x = (t >= off) ? sb[t - off] : 0;
        __syncthreads();
        sb[t] += x;
        __syncthreads();
    }
    if (t < NBLK) g_bscan[t] = sb[t] - v;
}

__global__ void scan_c_kernel() {
    int i = blockIdx.x * blockDim.x + threadIdx.x;
    if (i < NN) {
        int r = g_row[i] + g_bscan[i / SCAN_BLK];
        g_row[i] = r;
        g_woff[i] = r;
    }
    if (i == 0) g_row[NN] = ET;
}

// ve[h*8+d] = sum_c We[d, h*C+c] * a_edge[h, c], both layers
__global__ void compute_ve_kernel(const float* __restrict__ We1, const float* __restrict__ ae1v,
                                  const float* __restrict__ We2, const float* __restrict__ ae2v) {
    int t = threadIdx.x;
    if (t < 32) {
        int h = t / EDIM, d = t % EDIM;
        float s = 0.f;
        #pragma unroll
        for (int c = 0; c < 32; c++) s += We1[d * 128 + h * 32 + c] * ae1v[h * 32 + c];
        g_ve1[t] = s;
    } else if (t < 64) {
        int u = t - 32;
        int h = u / EDIM, d = u % EDIM;
        float s = 0.f;
        #pragma unroll
        for (int c = 0; c < 16; c++) s += We2[d * 64 + h * 16 + c] * ae2v[h * 16 + c];
        g_ve2[u] = s;
    }
}

// scatter edges to CSR slots; fold edge-attr attention dots for BOTH layers
__global__ void scatter_kernel(const float* __restrict__ edge_attr) {
    __shared__ float v1[HH * EDIM], v2[HH * EDIM];
    if (threadIdx.x < HH * EDIM) v1[threadIdx.x] = g_ve1[threadIdx.x];
    else if (threadIdx.x < 2 * HH * EDIM) v2[threadIdx.x - HH * EDIM] = g_ve2[threadIdx.x - HH * EDIM];
    __syncthreads();
    int e = blockIdx.x * blockDim.x + threadIdx.x;
    if (e >= ET) return;
    int d = g_dst[e];
    int p = atomicAdd(&g_woff[d], 1);
    g_csrc[p] = g_src[e];
    float4 a1 = make_float4(0.f, 0.f, 0.f, 0.f);
    float4 a2 = make_float4(0.f, 0.f, 0.f, 0.f);
    if (e < EE) {
        float4 ea0 = __ldg((const float4*)(edge_attr + (size_t)e * EDIM));
        float4 ea1 = __ldg((const float4*)(edge_attr + (size_t)e * EDIM + 4));
        float eav[8] = {ea0.x, ea0.y, ea0.z, ea0.w, ea1.x, ea1.y, ea1.z, ea1.w};
        float r1[HH], r2[HH];
        #pragma unroll
        for (int h = 0; h < HH; h++) {
            float s1 = 0.f, s2 = 0.f;
            #pragma unroll
            for (int k = 0; k < EDIM; k++) {
                s1 += eav[k] * v1[h * EDIM + k];
                s2 += eav[k] * v2[h * EDIM + k];
            }
            r1[h] = s1; r2[h] = s2;
        }
        a1 = make_float4(r1[0], r1[1], r1[2], r1[3]);
        a2 = make_float4(r2[0], r2[1], r2[2], r2[3]);
    }
    ((float4*)g_ae1)[p] = a1;
    ((float4*)g_ae2)[p] = a2;
}

// h = x @ W  (fused with a_src / a_dst per-head dots)
template <int FIN, int HC, int C>
__global__ void gemm_att_kernel(const float* __restrict__ x,
                                const float* __restrict__ W,
                                const float* __restrict__ a_src,
                                const float* __restrict__ a_dst) {
    constexpr int ROWS = 32;
    __shared__ float Ws[FIN * HC];
    __shared__ float xs[ROWS * FIN];
    __shared__ float asv[HC], adv[HC];
    int t = threadIdx.x;                       // blockDim.x == HC
    for (int i = t; i < FIN * HC; i += HC) Ws[i] = W[i];
    asv[t] = a_src[t];
    adv[t] = a_dst[t];
    int n0 = blockIdx.x * ROWS;
    for (int i = t; i < ROWS * FIN; i += HC) {
        int r = i / FIN, f = i % FIN;
        int n = n0 + r;
        xs[i] = (n < NN) ? x[(size_t)n * FIN + f] : 0.0f;
    }
    __syncthreads();

    for (int r = 0; r < ROWS; r += 4) {
        float acc[4] = {0.f, 0.f, 0.f, 0.f};
        #pragma unroll
        for (int f = 0; f < FIN; f++) {
            float w = Ws[f * HC + t];
            acc[0] += xs[(r + 0) * FIN + f] * w;
            acc[1] += xs[(r + 1) * FIN + f] * w;
            acc[2] += xs[(r + 2) * FIN + f] * w;
            acc[3] += xs[(r + 3) * FIN + f] * w;
        }
        #pragma unroll
        for (int j = 0; j < 4; j++) {
            int n = n0 + r + j;
            if (n < NN) g_h[(size_t)n * HC + t] = acc[j];
            float ps = acc[j] * asv[t];
            float pd = acc[j] * adv[t];
            #pragma unroll
            for (int off = C / 2; off > 0; off >>= 1) {
                ps += __shfl_xor_sync(0xffffffffu, ps, off);
                pd += __shfl_xor_sync(0xffffffffu, pd, off);
            }
            if ((t % C) == 0 && n < NN) {
                int head = t / C;
                g_as[n * HH + head] = ps;
                g_ad[n * HH + head] = pd;
            }
        }
    }
}

__device__ __forceinline__ float selh(float4 v, int h) {
    return h == 0 ? v.x : (h == 1 ? v.y : (h == 2 ? v.z : v.w));
}

// fully fused per-layer edge stage: alpha -> exp -> softmax denom -> weighted
// aggregation -> head mean + bias + ELU. One warp per destination node; no atomics.
template <int HC, int C>
__global__ void fused_layer_kernel(const float* __restrict__ b,
                                   float* __restrict__ out,
                                   const float* __restrict__ ae_csr) {
    int n = (blockIdx.x * blockDim.x + threadIdx.x) >> 5;
    int lane = threadIdx.x & 31;
    if (n >= NN) return;
    int rs = g_row[n], re = g_row[n + 1];
    float4 ad4 = *(const float4*)&g_ad[n * HH];
    const float4* aecsr4 = (const float4*)ae_csr;
    float4* exp4 = (float4*)g_exp;
    const float4* h4 = (const float4*)g_h;

    // ---- phase 1: exp(leaky(alpha)) per incoming edge + warp-wide denom ----
    float4 ds = make_float4(0.f, 0.f, 0.f, 0.f);
    for (int i = rs + lane; i < re; i += 32) {
        int s = g_csrc[i];
        float4 as4 = *(const float4*)&g_as[s * HH];
        float4 ae4 = aecsr4[i];
        float a0 = as4.x + ad4.x + ae4.x; a0 = a0 > 0.f ? a0 : NEG * a0;
        float a1 = as4.y + ad4.y + ae4.y; a1 = a1 > 0.f ? a1 : NEG * a1;
        float a2 = as4.z + ad4.z + ae4.z; a2 = a2 > 0.f ? a2 : NEG * a2;
        float a3 = as4.w + ad4.w + ae4.w; a3 = a3 > 0.f ? a3 : NEG * a3;
        float e0 = __expf(a0), e1 = __expf(a1), e2 = __expf(a2), e3 = __expf(a3);
        exp4[i] = make_float4(e0, e1, e2, e3);
        ds.x += e0; ds.y += e1; ds.z += e2; ds.w += e3;
    }
    #pragma unroll
    for (int off = 16; off > 0; off >>= 1) {
        ds.x += __shfl_xor_sync(0xffffffffu, ds.x, off);
        ds.y += __shfl_xor_sync(0xffffffffu, ds.y, off);
        ds.z += __shfl_xor_sync(0xffffffffu, ds.z, off);
        ds.w += __shfl_xor_sync(0xffffffffu, ds.w, off);
    }
    float4 rd = make_float4(1.f / (ds.x + EPSV), 1.f / (ds.y + EPSV),
                            1.f / (ds.z + EPSV), 1.f / (ds.w + EPSV));
    __syncwarp();

    // ---- phase 2: weighted gather of h[src], accumulate in registers ----
    if (HC == 128) {
        int head = lane >> 3;                       // lane*4 columns, C=32
        float rdh = selh(rd, head);
        float4 acc = make_float4(0.f, 0.f, 0.f, 0.f);
        int i = rs;
        for (; i + 1 < re; i += 2) {
            int s0 = g_csrc[i], s1 = g_csrc[i + 1];
            float4 e0 = exp4[i], e1 = exp4[i + 1];
            float w0 = selh(e0, head) * rdh;
            float w1 = selh(e1, head) * rdh;
            float4 h0 = h4[(size_t)s0 * 32 + lane];
            float4 h1 = h4[(size_t)s1 * 32 + lane];
            acc.x += w0 * h0.x + w1 * h1.x;
            acc.y += w0 * h0.y + w1 * h1.y;
            acc.z += w0 * h0.z + w1 * h1.z;
            acc.w += w0 * h0.w + w1 * h1.w;
        }
        if (i < re) {
            int s0 = g_csrc[i];
            float w0 = selh(exp4[i], head) * rdh;
            float4 h0 = h4[(size_t)s0 * 32 + lane];
            acc.x += w0 * h0.x; acc.y += w0 * h0.y;
            acc.z += w0 * h0.z; acc.w += w0 * h0.w;
        }
        // head mean: sum lanes {l, l+8, l+16, l+24}
        #pragma unroll
        for (int off = 8; off <= 16; off <<= 1) {
            acc.x += __shfl_xor_sync(0xffffffffu, acc.x, off);
            acc.y += __shfl_xor_sync(0xffffffffu, acc.y, off);
            acc.z += __shfl_xor_sync(0xffffffffu, acc.z, off);
            acc.w += __shfl_xor_sync(0xffffffffu, acc.w, off);
        }
        if (lane < 8) {
            float4 b4 = ((const float4*)b)[lane];
            float4 v;
            v.x = 0.25f * acc.x + b4.x; v.x = v.x > 0.f ? v.x : expm1f(v.x);
            v.y = 0.25f * acc.y + b4.y; v.y = v.y > 0.f ? v.y : expm1f(v.y);
            v.z = 0.25f * acc.z + b4.z; v.z = v.z > 0.f ? v.z : expm1f(v.z);
            v.w = 0.25f * acc.w + b4.w; v.w = v.w > 0.f ? v.w : expm1f(v.w);
            ((float4*)out)[(size_t)n * 8 + lane] = v;
        }
    } else {                                        // HC == 64, C == 16
        int l = lane & 15;
        int head = l >> 2;
        float rdh = selh(rd, head);
        float4 acc = make_float4(0.f, 0.f, 0.f, 0.f);
        for (int i = rs + (lane >> 4); i < re; i += 2) {
            int s = g_csrc[i];
            float w = selh(exp4[i], head) * rdh;
            float4 h0 = h4[(size_t)s * 16 + l];
            acc.x += w * h0.x; acc.y += w * h0.y;
            acc.z += w * h0.z; acc.w += w * h0.w;
        }
        // combine the two edge sub-groups (xor 16), then heads (xor 4, 8)
        #pragma unroll
        for (int k = 0; k < 3; k++) {
            int off = (k == 0) ? 16 : (k == 1 ? 4 : 8);
            acc.x += __shfl_xor_sync(0xffffffffu, acc.x, off);
            acc.y += __shfl_xor_sync(0xffffffffu, acc.y, off);
            acc.z += __shfl_xor_sync(0xffffffffu, acc.z, off);
            acc.w += __shfl_xor_sync(0xffffffffu, acc.w, off);
        }
        if (lane < 4) {
            float4 b4 = ((const float4*)b)[lane];
            float4 v;
            v.x = 0.25f * acc.x + b4.x; v.x = v.x > 0.f ? v.x : expm1f(v.x);
            v.y = 0.25f * acc.y + b4.y; v.y = v.y > 0.f ? v.y : expm1f(v.y);
            v.z = 0.25f * acc.z + b4.z; v.z = v.z > 0.f ? v.z : expm1f(v.z);
            v.w = 0.25f * acc.w + b4.w; v.w = v.w > 0.f ? v.w : expm1f(v.w);
            ((float4*)out)[(size_t)n * 4 + lane] = v;
        }
    }
}

// ---------------- launch ----------------
extern "C" void kernel_launch(void* const* d_in, const int* in_sizes, int n_in,
                              void* d_out, int out_size) {
    const float* x   = (const float*)d_in[0];
    const void*  ei  = d_in[1];
    const float* ea  = (const float*)d_in[2];
    const float* W1  = (const float*)d_in[3];
    const float* We1 = (const float*)d_in[4];
    const float* as1 = (const float*)d_in[5];
    const float* ad1 = (const float*)d_in[6];
    const float* ae1 = (const float*)d_in[7];
    const float* b1  = (const float*)d_in[8];
    const float* W2  = (const float*)d_in[9];
    const float* We2 = (const float*)d_in[10];
    const float* as2 = (const float*)d_in[11];
    const float* ad2 = (const float*)d_in[12];
    const float* ae2 = (const float*)d_in[13];
    const float* b2  = (const float*)d_in[14];
    float* out = (float*)d_out;

    float* x2p = nullptr;
    float* ae1p = nullptr;
    float* ae2p = nullptr;
    cudaGetSymbolAddress((void**)&x2p, g_x2);
    cudaGetSymbolAddress((void**)&ae1p, g_ae1);
    cudaGetSymbolAddress((void**)&ae2p, g_ae2);

    const int TB = 256;

    // graph preprocessing (once per call)
    detect_init_kernel<<<1, 1>>>();
    detect_kernel<<<(EE + TB - 1) / TB, TB>>>((const unsigned*)ei);
    zero_deg_kernel<<<(NN + TB - 1) / TB, TB>>>();
    prep_edges_kernel<<<(ET + TB - 1) / TB, TB>>>(ei);
    scan_a_kernel<<<NBLK, 256>>>();
    scan_b_kernel<<<1, 128>>>();
    scan_c_kernel<<<(NN + TB - 1) / TB, TB>>>();
    compute_ve_kernel<<<1, 64>>>(We1, ae1, We2, ae2);
    scatter_kernel<<<(ET + TB - 1) / TB, TB>>>(ea);

    // ---- layer 1: Fin=64, HC=128, C=32 ----
    gemm_att_kernel<64, 128, 32><<<(NN + 31) / 32, 128>>>(x, W1, as1, ad1);
    fused_layer_kernel<128, 32><<<(NN * 32 + TB - 1) / TB, TB>>>(b1, x2p, ae1p);

    // ---- layer 2: Fin=32, HC=64, C=16 ----
    gemm_att_kernel<32, 64, 16><<<(NN + 31) / 32, 64>>>(x2p, W2, as2, ad2);
    fused_layer_kernel<64, 16><<<(NN * 32 + TB - 1) / TB, TB>>>(b2, out, ae2p);
}

// round 11
// speedup vs baseline: 1.7836x; 1.0744x over previous
#include <cuda_runtime.h>
#include <math.h>

#define NN 100000
#define EE 1600000
#define ET 1700000          // EE + NN self loops
#define EDIM 8
#define HH 4
#define NEG 0.2f
#define EPSV 1e-16f
#define SCAN_BLK 1024
#define NBLK ((NN + SCAN_BLK - 1) / SCAN_BLK)   // 98
#define FULLM 0xffffffffu

// ---------------- static device scratch ----------------
__device__ int      g_src[ET];
__device__ int      g_dst[ET];
__device__ int      g_deg[NN];
__device__ int      g_row[NN + 1];
__device__ int      g_woff[NN];
__device__ int      g_bsum[NBLK];
__device__ int      g_bscan[NBLK];
__device__ int      g_csrc[ET];                 // CSR: src per slot
__device__ __align__(16) float g_ae1[ET * HH];  // CSR-ordered edge attention, layer 1
__device__ __align__(16) float g_ae2[ET * HH];  // CSR-ordered edge attention, layer 2
__device__ __align__(16) float g_h[NN * 128];   // per-node head features (max HC=128)
__device__ __align__(16) float g_x2[NN * 32];   // layer-2 input
__device__ __align__(16) float g_as[NN * HH];
__device__ __align__(16) float g_ad[NN * HH];
__device__ float    g_ve1[HH * EDIM];
__device__ float    g_ve2[HH * EDIM];
__device__ unsigned g_odd_or;

// ---------------- dtype detection for edge_index (int32 vs int64) ----------------
__global__ void detect_init_kernel() { g_odd_or = 0u; }

__global__ void detect_kernel(const unsigned* __restrict__ w) {
    int i = blockIdx.x * blockDim.x + threadIdx.x;
    unsigned acc = 0u;
    if (i < EE) acc = w[2 * (size_t)i + 1];
    #pragma unroll
    for (int off = 16; off > 0; off >>= 1)
        acc |= __shfl_xor_sync(FULLM, acc, off);
    if ((threadIdx.x & 31) == 0 && acc) atomicOr(&g_odd_or, acc);
}

__global__ void zero_deg_kernel() {
    int i = blockIdx.x * blockDim.x + threadIdx.x;
    if (i < NN) g_deg[i] = 0;
}

// decode edges (+ self loops), clamp, histogram of dst
__global__ void prep_edges_kernel(const void* __restrict__ eiv) {
    int e = blockIdx.x * blockDim.x + threadIdx.x;
    if (e >= ET) return;
    int s, d;
    if (e < EE) {
        if (g_odd_or != 0u) {                  // int32 layout
            const int* p = (const int*)eiv;
            s = p[e];
            d = p[(size_t)EE + e];
        } else {                               // int64 layout
            const long long* p = (const long long*)eiv;
            s = (int)p[e];
            d = (int)p[(size_t)EE + e];
        }
        s = s < 0 ? 0 : (s >= NN ? NN - 1 : s);
        d = d < 0 ? 0 : (d >= NN ? NN - 1 : d);
    } else {
        s = d = e - EE;
    }
    g_src[e] = s;
    g_dst[e] = d;
    atomicAdd(&g_deg[d], 1);
}

// ---------------- exclusive scan of g_deg -> g_row ----------------
__global__ void scan_a_kernel() {
    __shared__ int part[256];
    int b = blockIdx.x, t = threadIdx.x;
    int base = b * SCAN_BLK + t * 4;
    int v[4];
    #pragma unroll
    for (int j = 0; j < 4; j++) v[j] = (base + j < NN) ? g_deg[base + j] : 0;
    int tsum = v[0] + v[1] + v[2] + v[3];
    part[t] = tsum;
    __syncthreads();
    for (int off = 1; off < 256; off <<= 1) {
        int x = (t >= off) ? part[t - off] : 0;
        __syncthreads();
        part[t] += x;
        __syncthreads();
    }
    if (t == 255) g_bsum[b] = part[255];
    int run = part[t] - tsum;
    #pragma unroll
    for (int j = 0; j < 4; j++) {
        if (base + j < NN) g_row[base + j] = run;
        run += v[j];
    }
}

__global__ void scan_b_kernel() {
    __shared__ int sb[128];
    int t = threadIdx.x;
    int v = (t < NBLK) ? g_bsum[t] : 0;
    sb[t] = v;
    __syncthreads();
    for (int off = 1; off < 128; off <<= 1) {
        int x = (t >= off) ? sb[t - off] : 0;
        __syncthreads();
        sb[t] += x;
        __syncthreads();
    }
    if (t < NBLK) g_bscan[t] = sb[t] - v;
}

__global__ void scan_c_kernel() {
    int i = blockIdx.x * blockDim.x + threadIdx.x;
    if (i < NN) {
        int r = g_row[i] + g_bscan[i / SCAN_BLK];
        g_row[i] = r;
        g_woff[i] = r;
    }
    if (i == 0) g_row[NN] = ET;
}

// ve[h*8+d] = sum_c We[d, h*C+c] * a_edge[h, c], both layers
__global__ void compute_ve_kernel(const float* __restrict__ We1, const float* __restrict__ ae1v,
                                  const float* __restrict__ We2, const float* __restrict__ ae2v) {
    int t = threadIdx.x;
    if (t < 32) {
        int h = t / EDIM, d = t % EDIM;
        float s = 0.f;
        #pragma unroll
        for (int c = 0; c < 32; c++) s += We1[d * 128 + h * 32 + c] * ae1v[h * 32 + c];
        g_ve1[t] = s;
    } else if (t < 64) {
        int u = t - 32;
        int h = u / EDIM, d = u % EDIM;
        float s = 0.f;
        #pragma unroll
        for (int c = 0; c < 16; c++) s += We2[d * 64 + h * 16 + c] * ae2v[h * 16 + c];
        g_ve2[u] = s;
    }
}

// scatter edges to CSR slots; fold edge-attr attention dots for BOTH layers
__global__ void scatter_kernel(const float* __restrict__ edge_attr) {
    __shared__ float v1[HH * EDIM], v2[HH * EDIM];
    if (threadIdx.x < HH * EDIM) v1[threadIdx.x] = g_ve1[threadIdx.x];
    else if (threadIdx.x < 2 * HH * EDIM) v2[threadIdx.x - HH * EDIM] = g_ve2[threadIdx.x - HH * EDIM];
    __syncthreads();
    int e = blockIdx.x * blockDim.x + threadIdx.x;
    if (e >= ET) return;
    int d = g_dst[e];
    int p = atomicAdd(&g_woff[d], 1);
    g_csrc[p] = g_src[e];
    float4 a1 = make_float4(0.f, 0.f, 0.f, 0.f);
    float4 a2 = make_float4(0.f, 0.f, 0.f, 0.f);
    if (e < EE) {
        float4 ea0 = __ldg((const float4*)(edge_attr + (size_t)e * EDIM));
        float4 ea1 = __ldg((const float4*)(edge_attr + (size_t)e * EDIM + 4));
        float eav[8] = {ea0.x, ea0.y, ea0.z, ea0.w, ea1.x, ea1.y, ea1.z, ea1.w};
        float r1[HH], r2[HH];
        #pragma unroll
        for (int h = 0; h < HH; h++) {
            float s1 = 0.f, s2 = 0.f;
            #pragma unroll
            for (int k = 0; k < EDIM; k++) {
                s1 += eav[k] * v1[h * EDIM + k];
                s2 += eav[k] * v2[h * EDIM + k];
            }
            r1[h] = s1; r2[h] = s2;
        }
        a1 = make_float4(r1[0], r1[1], r1[2], r1[3]);
        a2 = make_float4(r2[0], r2[1], r2[2], r2[3]);
    }
    ((float4*)g_ae1)[p] = a1;
    ((float4*)g_ae2)[p] = a2;
}

// ---------------- register-tiled GEMMs (4x4 per thread) + attention dots ----------------
// layer 1: Fin=64, HC=128, C=32. 256 threads, 32 rows/block.
__global__ void gemm1_kernel(const float* __restrict__ x,
                             const float* __restrict__ W,
                             const float* __restrict__ a_src,
                             const float* __restrict__ a_dst) {
    __shared__ float Ws[64 * 128];
    __shared__ float xsT[64 * 36];     // transposed, pad 36 (16B-aligned rows)
    __shared__ float asv[128], adv[128];
    int t = threadIdx.x;
    for (int i = t; i < 64 * 128; i += 256) Ws[i] = W[i];
    if (t < 128) { asv[t] = a_src[t]; adv[t] = a_dst[t]; }
    int n0 = blockIdx.x * 32;
    for (int i = t; i < 2048; i += 256) {
        int r = i >> 6, f = i & 63;
        xsT[f * 36 + r] = x[(size_t)(n0 + r) * 64 + f];
    }
    __syncthreads();

    int tx = t & 31, ty = t >> 5;
    int c0 = tx * 4;
    float4 acc0 = {0,0,0,0}, acc1 = {0,0,0,0}, acc2 = {0,0,0,0}, acc3 = {0,0,0,0};
    #pragma unroll
    for (int f = 0; f < 64; f++) {
        float4 wv = *(const float4*)&Ws[f * 128 + c0];
        float4 xv = *(const float4*)&xsT[f * 36 + ty * 4];
        acc0.x += xv.x * wv.x; acc0.y += xv.x * wv.y; acc0.z += xv.x * wv.z; acc0.w += xv.x * wv.w;
        acc1.x += xv.y * wv.x; acc1.y += xv.y * wv.y; acc1.z += xv.y * wv.z; acc1.w += xv.y * wv.w;
        acc2.x += xv.z * wv.x; acc2.y += xv.z * wv.y; acc2.z += xv.z * wv.z; acc2.w += xv.z * wv.w;
        acc3.x += xv.w * wv.x; acc3.y += xv.w * wv.y; acc3.z += xv.w * wv.z; acc3.w += xv.w * wv.w;
    }
    int head = tx >> 3;
    float4 av = *(const float4*)&asv[c0];
    float4 dv = *(const float4*)&adv[c0];
    #pragma unroll
    for (int j = 0; j < 4; j++) {
        float4 a = (j == 0) ? acc0 : (j == 1) ? acc1 : (j == 2) ? acc2 : acc3;
        int n = n0 + ty * 4 + j;
        *(float4*)&g_h[(size_t)n * 128 + c0] = a;
        float ps = a.x * av.x + a.y * av.y + a.z * av.z + a.w * av.w;
        float pd = a.x * dv.x + a.y * dv.y + a.z * dv.z + a.w * dv.w;
        #pragma unroll
        for (int off = 1; off <= 4; off <<= 1) {
            ps += __shfl_xor_sync(FULLM, ps, off);
            pd += __shfl_xor_sync(FULLM, pd, off);
        }
        if ((tx & 7) == 0) {
            g_as[n * HH + head] = ps;
            g_ad[n * HH + head] = pd;
        }
    }
}

// layer 2: Fin=32, HC=64, C=16. 128 threads, 32 rows/block.
__global__ void gemm2_kernel(const float* __restrict__ x,
                             const float* __restrict__ W,
                             const float* __restrict__ a_src,
                             const float* __restrict__ a_dst) {
    __shared__ float Ws[32 * 64];
    __shared__ float xsT[32 * 36];
    __shared__ float asv[64], adv[64];
    int t = threadIdx.x;
    for (int i = t; i < 32 * 64; i += 128) Ws[i] = W[i];
    if (t < 64) { asv[t] = a_src[t]; adv[t] = a_dst[t]; }
    int n0 = blockIdx.x * 32;
    for (int i = t; i < 1024; i += 128) {
        int r = i >> 5, f = i & 31;
        xsT[f * 36 + r] = x[(size_t)(n0 + r) * 32 + f];
    }
    __syncthreads();

    int tx = t & 15, ty = t >> 4;
    int c0 = tx * 4;
    float4 acc0 = {0,0,0,0}, acc1 = {0,0,0,0}, acc2 = {0,0,0,0}, acc3 = {0,0,0,0};
    #pragma unroll
    for (int f = 0; f < 32; f++) {
        float4 wv = *(const float4*)&Ws[f * 64 + c0];
        float4 xv = *(const float4*)&xsT[f * 36 + ty * 4];
        acc0.x += xv.x * wv.x; acc0.y += xv.x * wv.y; acc0.z += xv.x * wv.z; acc0.w += xv.x * wv.w;
        acc1.x += xv.y * wv.x; acc1.y += xv.y * wv.y; acc1.z += xv.y * wv.z; acc1.w += xv.y * wv.w;
        acc2.x += xv.z * wv.x; acc2.y += xv.z * wv.y; acc2.z += xv.z * wv.z; acc2.w += xv.z * wv.w;
        acc3.x += xv.w * wv.x; acc3.y += xv.w * wv.y; acc3.z += xv.w * wv.z; acc3.w += xv.w * wv.w;
    }
    int head = tx >> 2;
    float4 av = *(const float4*)&asv[c0];
    float4 dv = *(const float4*)&adv[c0];
    #pragma unroll
    for (int j = 0; j < 4; j++) {
        float4 a = (j == 0) ? acc0 : (j == 1) ? acc1 : (j == 2) ? acc2 : acc3;
        int n = n0 + ty * 4 + j;
        *(float4*)&g_h[(size_t)n * 64 + c0] = a;
        float ps = a.x * av.x + a.y * av.y + a.z * av.z + a.w * av.w;
        float pd = a.x * dv.x + a.y * dv.y + a.z * dv.z + a.w * dv.w;
        #pragma unroll
        for (int off = 1; off <= 2; off <<= 1) {
            ps += __shfl_xor_sync(FULLM, ps, off);
            pd += __shfl_xor_sync(FULLM, pd, off);
        }
        if ((tx & 3) == 0) {
            g_as[n * HH + head] = ps;
            g_ad[n * HH + head] = pd;
        }
    }
}

__device__ __forceinline__ float selh(float4 v, int h) {
    return h == 0 ? v.x : (h == 1 ? v.y : (h == 2 ? v.z : v.w));
}

// single-pass fused layer (HC=128): exp kept in registers, shfl-broadcast,
// unnormalized accumulation, normalize by 1/denom at the end. No atomics, no g_exp.
__global__ void fused_layer128_kernel(const float* __restrict__ b,
                                      float* __restrict__ out,
                                      const float* __restrict__ ae_csr) {
    int n = (blockIdx.x * blockDim.x + threadIdx.x) >> 5;
    int lane = threadIdx.x & 31;
    if (n >= NN) return;
    int rs = g_row[n], re = g_row[n + 1];
    float4 ad4 = *(const float4*)&g_ad[n * HH];
    const float4* aecsr4 = (const float4*)ae_csr;
    const float4* h4 = (const float4*)g_h;
    int head = lane >> 3;

    float4 acc = make_float4(0.f, 0.f, 0.f, 0.f);
    float4 ds  = make_float4(0.f, 0.f, 0.f, 0.f);

    for (int i0 = rs; i0 < re; i0 += 32) {
        int i = i0 + lane;
        int s = 0;
        float e0 = 0.f, e1 = 0.f, e2 = 0.f, e3 = 0.f;
        if (i < re) {
            s = g_csrc[i];
            float4 as4 = *(const float4*)&g_as[s * HH];
            float4 ae4 = aecsr4[i];
            float a0 = as4.x + ad4.x + ae4.x; a0 = a0 > 0.f ? a0 : NEG * a0;
            float a1 = as4.y + ad4.y + ae4.y; a1 = a1 > 0.f ? a1 : NEG * a1;
            float a2 = as4.z + ad4.z + ae4.z; a2 = a2 > 0.f ? a2 : NEG * a2;
            float a3 = as4.w + ad4.w + ae4.w; a3 = a3 > 0.f ? a3 : NEG * a3;
            e0 = __expf(a0); e1 = __expf(a1); e2 = __expf(a2); e3 = __expf(a3);
        }
        ds.x += e0; ds.y += e1; ds.z += e2; ds.w += e3;
        int cnt = min(32, re - i0);
        int j = 0;
        for (; j + 1 < cnt; j += 2) {
            int sA = __shfl_sync(FULLM, s, j);
            int sB = __shfl_sync(FULLM, s, j + 1);
            float wA0 = __shfl_sync(FULLM, e0, j), wA1 = __shfl_sync(FULLM, e1, j);
            float wA2 = __shfl_sync(FULLM, e2, j), wA3 = __shfl_sync(FULLM, e3, j);
            float wB0 = __shfl_sync(FULLM, e0, j + 1), wB1 = __shfl_sync(FULLM, e1, j + 1);
            float wB2 = __shfl_sync(FULLM, e2, j + 1), wB3 = __shfl_sync(FULLM, e3, j + 1);
            float wA = head == 0 ? wA0 : head == 1 ? wA1 : head == 2 ? wA2 : wA3;
            float wB = head == 0 ? wB0 : head == 1 ? wB1 : head == 2 ? wB2 : wB3;
            float4 hA = h4[(size_t)sA * 32 + lane];
            float4 hB = h4[(size_t)sB * 32 + lane];
            acc.x += wA * hA.x + wB * hB.x;
            acc.y += wA * hA.y + wB * hB.y;
            acc.z += wA * hA.z + wB * hB.z;
            acc.w += wA * hA.w + wB * hB.w;
        }
        if (j < cnt) {
            int sA = __shfl_sync(FULLM, s, j);
            float wA0 = __shfl_sync(FULLM, e0, j), wA1 = __shfl_sync(FULLM, e1, j);
            float wA2 = __shfl_sync(FULLM, e2, j), wA3 = __shfl_sync(FULLM, e3, j);
            float wA = head == 0 ? wA0 : head == 1 ? wA1 : head == 2 ? wA2 : wA3;
            float4 hA = h4[(size_t)sA * 32 + lane];
            acc.x += wA * hA.x; acc.y += wA * hA.y;
            acc.z += wA * hA.z; acc.w += wA * hA.w;
        }
    }
    // denom across warp
    #pragma unroll
    for (int off = 16; off > 0; off >>= 1) {
        ds.x += __shfl_xor_sync(FULLM, ds.x, off);
        ds.y += __shfl_xor_sync(FULLM, ds.y, off);
        ds.z += __shfl_xor_sync(FULLM, ds.z, off);
        ds.w += __shfl_xor_sync(FULLM, ds.w, off);
    }
    float rdh = 1.f / (selh(ds, head) + EPSV);
    acc.x *= rdh; acc.y *= rdh; acc.z *= rdh; acc.w *= rdh;
    // head mean: sum lanes {l, l+8, l+16, l+24}
    #pragma unroll
    for (int off = 8; off <= 16; off <<= 1) {
        acc.x += __shfl_xor_sync(FULLM, acc.x, off);
        acc.y += __shfl_xor_sync(FULLM, acc.y, off);
        acc.z += __shfl_xor_sync(FULLM, acc.z, off);
        acc.w += __shfl_xor_sync(FULLM, acc.w, off);
    }
    if (lane < 8) {
        float4 b4 = ((const float4*)b)[lane];
        float4 v;
        v.x = 0.25f * acc.x + b4.x; v.x = v.x > 0.f ? v.x : expm1f(v.x);
        v.y = 0.25f * acc.y + b4.y; v.y = v.y > 0.f ? v.y : expm1f(v.y);
        v.z = 0.25f * acc.z + b4.z; v.z = v.z > 0.f ? v.z : expm1f(v.z);
        v.w = 0.25f * acc.w + b4.w; v.w = v.w > 0.f ? v.w : expm1f(v.w);
        ((float4*)out)[(size_t)n * 8 + lane] = v;
    }
}

// single-pass fused layer (HC=64): two half-warps process alternating edges.
__global__ void fused_layer64_kernel(const float* __restrict__ b,
                                     float* __restrict__ out,
                                     const float* __restrict__ ae_csr) {
    int n = (blockIdx.x * blockDim.x + threadIdx.x) >> 5;
    int lane = threadIdx.x & 31;
    if (n >= NN) return;
    int rs = g_row[n], re = g_row[n + 1];
    float4 ad4 = *(const float4*)&g_ad[n * HH];
    const float4* aecsr4 = (const float4*)ae_csr;
    const float4* h4 = (const float4*)g_h;
    int half = lane >> 4;
    int l = lane & 15;
    int head = l >> 2;

    float4 acc = make_float4(0.f, 0.f, 0.f, 0.f);
    float4 ds  = make_float4(0.f, 0.f, 0.f, 0.f);

    for (int i0 = rs; i0 < re; i0 += 32) {
        int i = i0 + lane;
        int s = 0;
        float e0 = 0.f, e1 = 0.f, e2 = 0.f, e3 = 0.f;
        if (i < re) {
            s = g_csrc[i];
            float4 as4 = *(const float4*)&g_as[s * HH];
            float4 ae4 = aecsr4[i];
            float a0 = as4.x + ad4.x + ae4.x; a0 = a0 > 0.f ? a0 : NEG * a0;
            float a1 = as4.y + ad4.y + ae4.y; a1 = a1 > 0.f ? a1 : NEG * a1;
            float a2 = as4.z + ad4.z + ae4.z; a2 = a2 > 0.f ? a2 : NEG * a2;
            float a3 = as4.w + ad4.w + ae4.w; a3 = a3 > 0.f ? a3 : NEG * a3;
            e0 = __expf(a0); e1 = __expf(a1); e2 = __expf(a2); e3 = __expf(a3);
        }
        ds.x += e0; ds.y += e1; ds.z += e2; ds.w += e3;
        int cnt = min(32, re - i0);
        for (int j0 = 0; j0 < cnt; j0 += 2) {
            int jj = j0 + half;
            int jc = jj < cnt ? jj : cnt - 1;          // keep shfl index valid, uniform flow
            int sj = __shfl_sync(FULLM, s, jc);
            float w0 = __shfl_sync(FULLM, e0, jc), w1 = __shfl_sync(FULLM, e1, jc);
            float w2 = __shfl_sync(FULLM, e2, jc), w3 = __shfl_sync(FULLM, e3, jc);
            if (jj < cnt) {
                float w = head == 0 ? w0 : head == 1 ? w1 : head == 2 ? w2 : w3;
                float4 hv = h4[(size_t)sj * 16 + l];
                acc.x += w * hv.x; acc.y += w * hv.y;
                acc.z += w * hv.z; acc.w += w * hv.w;
            }
        }
    }
    #pragma unroll
    for (int off = 16; off > 0; off >>= 1) {
        ds.x += __shfl_xor_sync(FULLM, ds.x, off);
        ds.y += __shfl_xor_sync(FULLM, ds.y, off);
        ds.z += __shfl_xor_sync(FULLM, ds.z, off);
        ds.w += __shfl_xor_sync(FULLM, ds.w, off);
    }
    float rdh = 1.f / (selh(ds, head) + EPSV);
    acc.x *= rdh; acc.y *= rdh; acc.z *= rdh; acc.w *= rdh;
    // combine halves (xor 16), then head mean (xor 4, 8)
    #pragma unroll
    for (int k = 0; k < 3; k++) {
        int off = (k == 0) ? 16 : (k == 1 ? 4 : 8);
        acc.x += __shfl_xor_sync(FULLM, acc.x, off);
        acc.y += __shfl_xor_sync(FULLM, acc.y, off);
        acc.z += __shfl_xor_sync(FULLM, acc.z, off);
        acc.w += __shfl_xor_sync(FULLM, acc.w, off);
    }
    if (lane < 4) {
        float4 b4 = ((const float4*)b)[lane];
        float4 v;
        v.x = 0.25f * acc.x + b4.x; v.x = v.x > 0.f ? v.x : expm1f(v.x);
        v.y = 0.25f * acc.y + b4.y; v.y = v.y > 0.f ? v.y : expm1f(v.y);
        v.z = 0.25f * acc.z + b4.z; v.z = v.z > 0.f ? v.z : expm1f(v.z);
        v.w = 0.25f * acc.w + b4.w; v.w = v.w > 0.f ? v.w : expm1f(v.w);
        ((float4*)out)[(size_t)n * 4 + lane] = v;
    }
}

// ---------------- launch ----------------
extern "C" void kernel_launch(void* const* d_in, const int* in_sizes, int n_in,
                              void* d_out, int out_size) {
    const float* x   = (const float*)d_in[0];
    const void*  ei  = d_in[1];
    const float* ea  = (const float*)d_in[2];
    const float* W1  = (const float*)d_in[3];
    const float* We1 = (const float*)d_in[4];
    const float* as1 = (const float*)d_in[5];
    const float* ad1 = (const float*)d_in[6];
    const float* ae1 = (const float*)d_in[7];
    const float* b1  = (const float*)d_in[8];
    const float* W2  = (const float*)d_in[9];
    const float* We2 = (const float*)d_in[10];
    const float* as2 = (const float*)d_in[11];
    const float* ad2 = (const float*)d_in[12];
    const float* ae2 = (const float*)d_in[13];
    const float* b2  = (const float*)d_in[14];
    float* out = (float*)d_out;

    float* x2p = nullptr;
    float* ae1p = nullptr;
    float* ae2p = nullptr;
    cudaGetSymbolAddress((void**)&x2p, g_x2);
    cudaGetSymbolAddress((void**)&ae1p, g_ae1);
    cudaGetSymbolAddress((void**)&ae2p, g_ae2);

    const int TB = 256;

    // graph preprocessing (once per call)
    detect_init_kernel<<<1, 1>>>();
    detect_kernel<<<(EE + TB - 1) / TB, TB>>>((const unsigned*)ei);
    zero_deg_kernel<<<(NN + TB - 1) / TB, TB>>>();
    prep_edges_kernel<<<(ET + TB - 1) / TB, TB>>>(ei);
    scan_a_kernel<<<NBLK, 256>>>();
    scan_b_kernel<<<1, 128>>>();
    scan_c_kernel<<<(NN + TB - 1) / TB, TB>>>();
    compute_ve_kernel<<<1, 64>>>(We1, ae1, We2, ae2);
    scatter_kernel<<<(ET + TB - 1) / TB, TB>>>(ea);

    // ---- layer 1: Fin=64, HC=128, C=32 ----
    gemm1_kernel<<<NN / 32, 256>>>(x, W1, as1, ad1);
    fused_layer128_kernel<<<(NN * 32 + TB - 1) / TB, TB>>>(b1, x2p, ae1p);

    // ---- layer 2: Fin=32, HC=64, C=16 ----
    gemm2_kernel<<<NN / 32, 128>>>(x2p, W2, as2, ad2);
    fused_layer64_kernel<<<(NN * 32 + TB - 1) / TB, TB>>>(b2, out, ae2p);
}

// round 12
// speedup vs baseline: 1.9022x; 1.0665x over previous
#include <cuda_runtime.h>
#include <cuda_fp16.h>
#include <math.h>

#define NN 100000
#define EE 1600000
#define ET 1700000          // EE + NN self loops
#define EDIM 8
#define HH 4
#define NEG 0.2f
#define EPSV 1e-16f
#define SCAN_BLK 1024
#define NBLK ((NN + SCAN_BLK - 1) / SCAN_BLK)   // 98
#define FULLM 0xffffffffu

// ---------------- static device scratch ----------------
__device__ int      g_src[ET];
__device__ int      g_dst[ET];
__device__ int      g_deg[NN];
__device__ int      g_row[NN + 1];
__device__ int      g_woff[NN];
__device__ int      g_bsum[NBLK];
__device__ int      g_bscan[NBLK];
__device__ int      g_csrc[ET];                 // CSR: src per slot
__device__ __align__(16) float  g_ae1[ET * HH]; // CSR-ordered edge attention, layer 1
__device__ __align__(16) float  g_ae2[ET * HH]; // CSR-ordered edge attention, layer 2
__device__ __align__(16) __half g_h16[NN * 128];// per-node head features, fp16 payload
__device__ __align__(16) float  g_x2[NN * 32];  // layer-2 input (fp32)
__device__ __align__(16) float  g_as[NN * HH];
__device__ __align__(16) float  g_ad[NN * HH];
__device__ float    g_ve1[HH * EDIM];
__device__ float    g_ve2[HH * EDIM];
__device__ unsigned g_odd_or;

// ---------------- dtype detection for edge_index (int32 vs int64) ----------------
__global__ void detect_init_kernel() { g_odd_or = 0u; }

__global__ void detect_kernel(const unsigned* __restrict__ w) {
    int i = blockIdx.x * blockDim.x + threadIdx.x;
    unsigned acc = 0u;
    if (i < EE) acc = w[2 * (size_t)i + 1];
    #pragma unroll
    for (int off = 16; off > 0; off >>= 1)
        acc |= __shfl_xor_sync(FULLM, acc, off);
    if ((threadIdx.x & 31) == 0 && acc) atomicOr(&g_odd_or, acc);
}

__global__ void zero_deg_kernel() {
    int i = blockIdx.x * blockDim.x + threadIdx.x;
    if (i < NN) g_deg[i] = 0;
}

// decode edges (+ self loops), clamp, histogram of dst
__global__ void prep_edges_kernel(const void* __restrict__ eiv) {
    int e = blockIdx.x * blockDim.x + threadIdx.x;
    if (e >= ET) return;
    int s, d;
    if (e < EE) {
        if (g_odd_or != 0u) {                  // int32 layout
            const int* p = (const int*)eiv;
            s = p[e];
            d = p[(size_t)EE + e];
        } else {                               // int64 layout
            const long long* p = (const long long*)eiv;
            s = (int)p[e];
            d = (int)p[(size_t)EE + e];
        }
        s = s < 0 ? 0 : (s >= NN ? NN - 1 : s);
        d = d < 0 ? 0 : (d >= NN ? NN - 1 : d);
    } else {
        s = d = e - EE;
    }
    g_src[e] = s;
    g_dst[e] = d;
    atomicAdd(&g_deg[d], 1);
}

// ---------------- exclusive scan of g_deg -> g_row ----------------
__global__ void scan_a_kernel() {
    __shared__ int part[256];
    int b = blockIdx.x, t = threadIdx.x;
    int base = b * SCAN_BLK + t * 4;
    int v[4];
    #pragma unroll
    for (int j = 0; j < 4; j++) v[j] = (base + j < NN) ? g_deg[base + j] : 0;
    int tsum = v[0] + v[1] + v[2] + v[3];
    part[t] = tsum;
    __syncthreads();
    for (int off = 1; off < 256; off <<= 1) {
        int x = (t >= off) ? part[t - off] : 0;
        __syncthreads();
        part[t] += x;
        __syncthreads();
    }
    if (t == 255) g_bsum[b] = part[255];
    int run = part[t] - tsum;
    #pragma unroll
    for (int j = 0; j < 4; j++) {
        if (base + j < NN) g_row[base + j] = run;
        run += v[j];
    }
}

__global__ void scan_b_kernel() {
    __shared__ int sb[128];
    int t = threadIdx.x;
    int v = (t < NBLK) ? g_bsum[t] : 0;
    sb[t] = v;
    __syncthreads();
    for (int off = 1; off < 128; off <<= 1) {
        int x = (t >= off) ? sb[t - off] : 0;
        __syncthreads();
        sb[t] += x;
        __syncthreads();
    }
    if (t < NBLK) g_bscan[t] = sb[t] - v;
}

__global__ void scan_c_kernel() {
    int i = blockIdx.x * blockDim.x + threadIdx.x;
    if (i < NN) {
        int r = g_row[i] + g_bscan[i / SCAN_BLK];
        g_row[i] = r;
        g_woff[i] = r;
    }
    if (i == 0) g_row[NN] = ET;
}

// ve[h*8+d] = sum_c We[d, h*C+c] * a_edge[h, c], both layers
__global__ void compute_ve_kernel(const float* __restrict__ We1, const float* __restrict__ ae1v,
                                  const float* __restrict__ We2, const float* __restrict__ ae2v) {
    int t = threadIdx.x;
    if (t < 32) {
        int h = t / EDIM, d = t % EDIM;
        float s = 0.f;
        #pragma unroll
        for (int c = 0; c < 32; c++) s += We1[d * 128 + h * 32 + c] * ae1v[h * 32 + c];
        g_ve1[t] = s;
    } else if (t < 64) {
        int u = t - 32;
        int h = u / EDIM, d = u % EDIM;
        float s = 0.f;
        #pragma unroll
        for (int c = 0; c < 16; c++) s += We2[d * 64 + h * 16 + c] * ae2v[h * 16 + c];
        g_ve2[u] = s;
    }
}

// scatter edges to CSR slots; fold edge-attr attention dots for BOTH layers
__global__ void scatter_kernel(const float* __restrict__ edge_attr) {
    __shared__ float v1[HH * EDIM], v2[HH * EDIM];
    if (threadIdx.x < HH * EDIM) v1[threadIdx.x] = g_ve1[threadIdx.x];
    else if (threadIdx.x < 2 * HH * EDIM) v2[threadIdx.x - HH * EDIM] = g_ve2[threadIdx.x - HH * EDIM];
    __syncthreads();
    int e = blockIdx.x * blockDim.x + threadIdx.x;
    if (e >= ET) return;
    int d = g_dst[e];
    int p = atomicAdd(&g_woff[d], 1);
    g_csrc[p] = g_src[e];
    float4 a1 = make_float4(0.f, 0.f, 0.f, 0.f);
    float4 a2 = make_float4(0.f, 0.f, 0.f, 0.f);
    if (e < EE) {
        float4 ea0 = __ldg((const float4*)(edge_attr + (size_t)e * EDIM));
        float4 ea1 = __ldg((const float4*)(edge_attr + (size_t)e * EDIM + 4));
        float eav[8] = {ea0.x, ea0.y, ea0.z, ea0.w, ea1.x, ea1.y, ea1.z, ea1.w};
        float r1[HH], r2[HH];
        #pragma unroll
        for (int h = 0; h < HH; h++) {
            float s1 = 0.f, s2 = 0.f;
            #pragma unroll
            for (int k = 0; k < EDIM; k++) {
                s1 += eav[k] * v1[h * EDIM + k];
                s2 += eav[k] * v2[h * EDIM + k];
            }
            r1[h] = s1; r2[h] = s2;
        }
        a1 = make_float4(r1[0], r1[1], r1[2], r1[3]);
        a2 = make_float4(r2[0], r2[1], r2[2], r2[3]);
    }
    ((float4*)g_ae1)[p] = a1;
    ((float4*)g_ae2)[p] = a2;
}

__device__ __forceinline__ uint2 pack_half4(float4 a) {
    __half2 h01 = __float22half2_rn(make_float2(a.x, a.y));
    __half2 h23 = __float22half2_rn(make_float2(a.z, a.w));
    uint2 u;
    u.x = *reinterpret_cast<unsigned*>(&h01);
    u.y = *reinterpret_cast<unsigned*>(&h23);
    return u;
}

// ---------------- register-tiled GEMMs (4x4 per thread) + attention dots ----------------
// layer 1: Fin=64, HC=128, C=32. 256 threads, 32 rows/block. fp16 h store, fp32 att dots.
__global__ void gemm1_kernel(const float* __restrict__ x,
                             const float* __restrict__ W,
                             const float* __restrict__ a_src,
                             const float* __restrict__ a_dst) {
    __shared__ float Ws[64 * 128];
    __shared__ float xsT[64 * 36];     // transposed, pad 36 (16B-aligned rows)
    __shared__ float asv[128], adv[128];
    int t = threadIdx.x;
    for (int i = t; i < 64 * 128; i += 256) Ws[i] = W[i];
    if (t < 128) { asv[t] = a_src[t]; adv[t] = a_dst[t]; }
    int n0 = blockIdx.x * 32;
    for (int i = t; i < 2048; i += 256) {
        int r = i >> 6, f = i & 63;
        xsT[f * 36 + r] = x[(size_t)(n0 + r) * 64 + f];
    }
    __syncthreads();

    int tx = t & 31, ty = t >> 5;
    int c0 = tx * 4;
    float4 acc0 = {0,0,0,0}, acc1 = {0,0,0,0}, acc2 = {0,0,0,0}, acc3 = {0,0,0,0};
    #pragma unroll
    for (int f = 0; f < 64; f++) {
        float4 wv = *(const float4*)&Ws[f * 128 + c0];
        float4 xv = *(const float4*)&xsT[f * 36 + ty * 4];
        acc0.x += xv.x * wv.x; acc0.y += xv.x * wv.y; acc0.z += xv.x * wv.z; acc0.w += xv.x * wv.w;
        acc1.x += xv.y * wv.x; acc1.y += xv.y * wv.y; acc1.z += xv.y * wv.z; acc1.w += xv.y * wv.w;
        acc2.x += xv.z * wv.x; acc2.y += xv.z * wv.y; acc2.z += xv.z * wv.z; acc2.w += xv.z * wv.w;
        acc3.x += xv.w * wv.x; acc3.y += xv.w * wv.y; acc3.z += xv.w * wv.z; acc3.w += xv.w * wv.w;
    }
    int head = tx >> 3;
    float4 av = *(const float4*)&asv[c0];
    float4 dv = *(const float4*)&adv[c0];
    #pragma unroll
    for (int j = 0; j < 4; j++) {
        float4 a = (j == 0) ? acc0 : (j == 1) ? acc1 : (j == 2) ? acc2 : acc3;
        int n = n0 + ty * 4 + j;
        ((uint2*)g_h16)[(size_t)n * 32 + tx] = pack_half4(a);
        float ps = a.x * av.x + a.y * av.y + a.z * av.z + a.w * av.w;
        float pd = a.x * dv.x + a.y * dv.y + a.z * dv.z + a.w * dv.w;
        #pragma unroll
        for (int off = 1; off <= 4; off <<= 1) {
            ps += __shfl_xor_sync(FULLM, ps, off);
            pd += __shfl_xor_sync(FULLM, pd, off);
        }
        if ((tx & 7) == 0) {
            g_as[n * HH + head] = ps;
            g_ad[n * HH + head] = pd;
        }
    }
}

// layer 2: Fin=32, HC=64, C=16. 128 threads, 32 rows/block.
__global__ void gemm2_kernel(const float* __restrict__ x,
                             const float* __restrict__ W,
                             const float* __restrict__ a_src,
                             const float* __restrict__ a_dst) {
    __shared__ float Ws[32 * 64];
    __shared__ float xsT[32 * 36];
    __shared__ float asv[64], adv[64];
    int t = threadIdx.x;
    for (int i = t; i < 32 * 64; i += 128) Ws[i] = W[i];
    if (t < 64) { asv[t] = a_src[t]; adv[t] = a_dst[t]; }
    int n0 = blockIdx.x * 32;
    for (int i = t; i < 1024; i += 128) {
        int r = i >> 5, f = i & 31;
        xsT[f * 36 + r] = x[(size_t)(n0 + r) * 32 + f];
    }
    __syncthreads();

    int tx = t & 15, ty = t >> 4;
    int c0 = tx * 4;
    float4 acc0 = {0,0,0,0}, acc1 = {0,0,0,0}, acc2 = {0,0,0,0}, acc3 = {0,0,0,0};
    #pragma unroll
    for (int f = 0; f < 32; f++) {
        float4 wv = *(const float4*)&Ws[f * 64 + c0];
        float4 xv = *(const float4*)&xsT[f * 36 + ty * 4];
        acc0.x += xv.x * wv.x; acc0.y += xv.x * wv.y; acc0.z += xv.x * wv.z; acc0.w += xv.x * wv.w;
        acc1.x += xv.y * wv.x; acc1.y += xv.y * wv.y; acc1.z += xv.y * wv.z; acc1.w += xv.y * wv.w;
        acc2.x += xv.z * wv.x; acc2.y += xv.z * wv.y; acc2.z += xv.z * wv.z; acc2.w += xv.z * wv.w;
        acc3.x += xv.w * wv.x; acc3.y += xv.w * wv.y; acc3.z += xv.w * wv.z; acc3.w += xv.w * wv.w;
    }
    int head = tx >> 2;
    float4 av = *(const float4*)&asv[c0];
    float4 dv = *(const float4*)&adv[c0];
    #pragma unroll
    for (int j = 0; j < 4; j++) {
        float4 a = (j == 0) ? acc0 : (j == 1) ? acc1 : (j == 2) ? acc2 : acc3;
        int n = n0 + ty * 4 + j;
        ((uint2*)g_h16)[(size_t)n * 16 + tx] = pack_half4(a);
        float ps = a.x * av.x + a.y * av.y + a.z * av.z + a.w * av.w;
        float pd = a.x * dv.x + a.y * dv.y + a.z * dv.z + a.w * dv.w;
        #pragma unroll
        for (int off = 1; off <= 2; off <<= 1) {
            ps += __shfl_xor_sync(FULLM, ps, off);
            pd += __shfl_xor_sync(FULLM, pd, off);
        }
        if ((tx & 3) == 0) {
            g_as[n * HH + head] = ps;
            g_ad[n * HH + head] = pd;
        }
    }
}

__device__ __forceinline__ float selh(float4 v, int h) {
    return h == 0 ? v.x : (h == 1 ? v.y : (h == 2 ? v.z : v.w));
}

__device__ __forceinline__ void fma_half4(float4& acc, float w, uint2 u) {
    float2 f0 = __half22float2(*reinterpret_cast<__half2*>(&u.x));
    float2 f1 = __half22float2(*reinterpret_cast<__half2*>(&u.y));
    acc.x += w * f0.x; acc.y += w * f0.y;
    acc.z += w * f1.x; acc.w += w * f1.y;
}

// single-pass fused layer (HC=128): exp in registers, shfl-broadcast,
// unnormalized accumulation, normalize at end. fp16 h payload.
__global__ void fused_layer128_kernel(const float* __restrict__ b,
                                      float* __restrict__ out,
                                      const float* __restrict__ ae_csr) {
    int n = (blockIdx.x * blockDim.x + threadIdx.x) >> 5;
    int lane = threadIdx.x & 31;
    if (n >= NN) return;
    int rs = g_row[n], re = g_row[n + 1];
    float4 ad4 = *(const float4*)&g_ad[n * HH];
    const float4* aecsr4 = (const float4*)ae_csr;
    const uint2* h2 = (const uint2*)g_h16;
    int head = lane >> 3;

    float4 acc = make_float4(0.f, 0.f, 0.f, 0.f);
    float4 ds  = make_float4(0.f, 0.f, 0.f, 0.f);

    for (int i0 = rs; i0 < re; i0 += 32) {
        int i = i0 + lane;
        int s = 0;
        float e0 = 0.f, e1 = 0.f, e2 = 0.f, e3 = 0.f;
        if (i < re) {
            s = g_csrc[i];
            float4 as4 = *(const float4*)&g_as[s * HH];
            float4 ae4 = aecsr4[i];
            float a0 = as4.x + ad4.x + ae4.x; a0 = a0 > 0.f ? a0 : NEG * a0;
            float a1 = as4.y + ad4.y + ae4.y; a1 = a1 > 0.f ? a1 : NEG * a1;
            float a2 = as4.z + ad4.z + ae4.z; a2 = a2 > 0.f ? a2 : NEG * a2;
            float a3 = as4.w + ad4.w + ae4.w; a3 = a3 > 0.f ? a3 : NEG * a3;
            e0 = __expf(a0); e1 = __expf(a1); e2 = __expf(a2); e3 = __expf(a3);
        }
        ds.x += e0; ds.y += e1; ds.z += e2; ds.w += e3;
        int cnt = min(32, re - i0);
        int j = 0;
        for (; j + 1 < cnt; j += 2) {
            int sA = __shfl_sync(FULLM, s, j);
            int sB = __shfl_sync(FULLM, s, j + 1);
            float wA0 = __shfl_sync(FULLM, e0, j), wA1 = __shfl_sync(FULLM, e1, j);
            float wA2 = __shfl_sync(FULLM, e2, j), wA3 = __shfl_sync(FULLM, e3, j);
            float wB0 = __shfl_sync(FULLM, e0, j + 1), wB1 = __shfl_sync(FULLM, e1, j + 1);
            float wB2 = __shfl_sync(FULLM, e2, j + 1), wB3 = __shfl_sync(FULLM, e3, j + 1);
            float wA = head == 0 ? wA0 : head == 1 ? wA1 : head == 2 ? wA2 : wA3;
            float wB = head == 0 ? wB0 : head == 1 ? wB1 : head == 2 ? wB2 : wB3;
            uint2 hA = h2[(size_t)sA * 32 + lane];
            uint2 hB = h2[(size_t)sB * 32 + lane];
            fma_half4(acc, wA, hA);
            fma_half4(acc, wB, hB);
        }
        if (j < cnt) {
            int sA = __shfl_sync(FULLM, s, j);
            float wA0 = __shfl_sync(FULLM, e0, j), wA1 = __shfl_sync(FULLM, e1, j);
            float wA2 = __shfl_sync(FULLM, e2, j), wA3 = __shfl_sync(FULLM, e3, j);
            float wA = head == 0 ? wA0 : head == 1 ? wA1 : head == 2 ? wA2 : wA3;
            uint2 hA = h2[(size_t)sA * 32 + lane];
            fma_half4(acc, wA, hA);
        }
    }
    #pragma unroll
    for (int off = 16; off > 0; off >>= 1) {
        ds.x += __shfl_xor_sync(FULLM, ds.x, off);
        ds.y += __shfl_xor_sync(FULLM, ds.y, off);
        ds.z += __shfl_xor_sync(FULLM, ds.z, off);
        ds.w += __shfl_xor_sync(FULLM, ds.w, off);
    }
    float rdh = 1.f / (selh(ds, head) + EPSV);
    acc.x *= rdh; acc.y *= rdh; acc.z *= rdh; acc.w *= rdh;
    // head mean: sum lanes {l, l+8, l+16, l+24}
    #pragma unroll
    for (int off = 8; off <= 16; off <<= 1) {
        acc.x += __shfl_xor_sync(FULLM, acc.x, off);
        acc.y += __shfl_xor_sync(FULLM, acc.y, off);
        acc.z += __shfl_xor_sync(FULLM, acc.z, off);
        acc.w += __shfl_xor_sync(FULLM, acc.w, off);
    }
    if (lane < 8) {
        float4 b4 = ((const float4*)b)[lane];
        float4 v;
        v.x = 0.25f * acc.x + b4.x; v.x = v.x > 0.f ? v.x : expm1f(v.x);
        v.y = 0.25f * acc.y + b4.y; v.y = v.y > 0.f ? v.y : expm1f(v.y);
        v.z = 0.25f * acc.z + b4.z; v.z = v.z > 0.f ? v.z : expm1f(v.z);
        v.w = 0.25f * acc.w + b4.w; v.w = v.w > 0.f ? v.w : expm1f(v.w);
        ((float4*)out)[(size_t)n * 8 + lane] = v;
    }
}

// single-pass fused layer (HC=64): two half-warps process alternating edges.
__global__ void fused_layer64_kernel(const float* __restrict__ b,
                                     float* __restrict__ out,
                                     const float* __restrict__ ae_csr) {
    int n = (blockIdx.x * blockDim.x + threadIdx.x) >> 5;
    int lane = threadIdx.x & 31;
    if (n >= NN) return;
    int rs = g_row[n], re = g_row[n + 1];
    float4 ad4 = *(const float4*)&g_ad[n * HH];
    const float4* aecsr4 = (const float4*)ae_csr;
    const uint2* h2 = (const uint2*)g_h16;
    int half = lane >> 4;
    int l = lane & 15;
    int head = l >> 2;

    float4 acc = make_float4(0.f, 0.f, 0.f, 0.f);
    float4 ds  = make_float4(0.f, 0.f, 0.f, 0.f);

    for (int i0 = rs; i0 < re; i0 += 32) {
        int i = i0 + lane;
        int s = 0;
        float e0 = 0.f, e1 = 0.f, e2 = 0.f, e3 = 0.f;
        if (i < re) {
            s = g_csrc[i];
            float4 as4 = *(const float4*)&g_as[s * HH];
            float4 ae4 = aecsr4[i];
            float a0 = as4.x + ad4.x + ae4.x; a0 = a0 > 0.f ? a0 : NEG * a0;
            float a1 = as4.y + ad4.y + ae4.y; a1 = a1 > 0.f ? a1 : NEG * a1;
            float a2 = as4.z + ad4.z + ae4.z; a2 = a2 > 0.f ? a2 : NEG * a2;
            float a3 = as4.w + ad4.w + ae4.w; a3 = a3 > 0.f ? a3 : NEG * a3;
            e0 = __expf(a0); e1 = __expf(a1); e2 = __expf(a2); e3 = __expf(a3);
        }
        ds.x += e0; ds.y += e1; ds.z += e2; ds.w += e3;
        int cnt = min(32, re - i0);
        for (int j0 = 0; j0 < cnt; j0 += 2) {
            int jj = j0 + half;
            int jc = jj < cnt ? jj : cnt - 1;
            int sj = __shfl_sync(FULLM, s, jc);
            float w0 = __shfl_sync(FULLM, e0, jc), w1 = __shfl_sync(FULLM, e1, jc);
            float w2 = __shfl_sync(FULLM, e2, jc), w3 = __shfl_sync(FULLM, e3, jc);
            if (jj < cnt) {
                float w = head == 0 ? w0 : head == 1 ? w1 : head == 2 ? w2 : w3;
                uint2 hv = h2[(size_t)sj * 16 + l];
                fma_half4(acc, w, hv);
            }
        }
    }
    #pragma unroll
    for (int off = 16; off > 0; off >>= 1) {
        ds.x += __shfl_xor_sync(FULLM, ds.x, off);
        ds.y += __shfl_xor_sync(FULLM, ds.y, off);
        ds.z += __shfl_xor_sync(FULLM, ds.z, off);
        ds.w += __shfl_xor_sync(FULLM, ds.w, off);
    }
    float rdh = 1.f / (selh(ds, head) + EPSV);
    acc.x *= rdh; acc.y *= rdh; acc.z *= rdh; acc.w *= rdh;
    #pragma unroll
    for (int k = 0; k < 3; k++) {
        int off = (k == 0) ? 16 : (k == 1 ? 4 : 8);
        acc.x += __shfl_xor_sync(FULLM, acc.x, off);
        acc.y += __shfl_xor_sync(FULLM, acc.y, off);
        acc.z += __shfl_xor_sync(FULLM, acc.z, off);
        acc.w += __shfl_xor_sync(FULLM, acc.w, off);
    }
    if (lane < 4) {
        float4 b4 = ((const float4*)b)[lane];
        float4 v;
        v.x = 0.25f * acc.x + b4.x; v.x = v.x > 0.f ? v.x : expm1f(v.x);
        v.y = 0.25f * acc.y + b4.y; v.y = v.y > 0.f ? v.y : expm1f(v.y);
        v.z = 0.25f * acc.z + b4.z; v.z = v.z > 0.f ? v.z : expm1f(v.z);
        v.w = 0.25f * acc.w + b4.w; v.w = v.w > 0.f ? v.w : expm1f(v.w);
        ((float4*)out)[(size_t)n * 4 + lane] = v;
    }
}

// ---------------- launch ----------------
extern "C" void kernel_launch(void* const* d_in, const int* in_sizes, int n_in,
                              void* d_out, int out_size) {
    const float* x   = (const float*)d_in[0];
    const void*  ei  = d_in[1];
    const float* ea  = (const float*)d_in[2];
    const float* W1  = (const float*)d_in[3];
    const float* We1 = (const float*)d_in[4];
    const float* as1 = (const float*)d_in[5];
    const float* ad1 = (const float*)d_in[6];
    const float* ae1 = (const float*)d_in[7];
    const float* b1  = (const float*)d_in[8];
    const float* W2  = (const float*)d_in[9];
    const float* We2 = (const float*)d_in[10];
    const float* as2 = (const float*)d_in[11];
    const float* ad2 = (const float*)d_in[12];
    const float* ae2 = (const float*)d_in[13];
    const float* b2  = (const float*)d_in[14];
    float* out = (float*)d_out;

    float* x2p = nullptr;
    float* ae1p = nullptr;
    float* ae2p = nullptr;
    cudaGetSymbolAddress((void**)&x2p, g_x2);
    cudaGetSymbolAddress((void**)&ae1p, g_ae1);
    cudaGetSymbolAddress((void**)&ae2p, g_ae2);

    const int TB = 256;

    // graph preprocessing (once per call)
    detect_init_kernel<<<1, 1>>>();
    detect_kernel<<<(EE + TB - 1) / TB, TB>>>((const unsigned*)ei);
    zero_deg_kernel<<<(NN + TB - 1) / TB, TB>>>();
    prep_edges_kernel<<<(ET + TB - 1) / TB, TB>>>(ei);
    scan_a_kernel<<<NBLK, 256>>>();
    scan_b_kernel<<<1, 128>>>();
    scan_c_kernel<<<(NN + TB - 1) / TB, TB>>>();
    compute_ve_kernel<<<1, 64>>>(We1, ae1, We2, ae2);
    scatter_kernel<<<(ET + TB - 1) / TB, TB>>>(ea);

    // ---- layer 1: Fin=64, HC=128, C=32 ----
    gemm1_kernel<<<NN / 32, 256>>>(x, W1, as1, ad1);
    fused_layer128_kernel<<<(NN * 32 + TB - 1) / TB, TB>>>(b1, x2p, ae1p);

    // ---- layer 2: Fin=32, HC=64, C=16 ----
    gemm2_kernel<<<NN / 32, 128>>>(x2p, W2, as2, ad2);
    fused_layer64_kernel<<<(NN * 32 + TB - 1) / TB, TB>>>(b2, out, ae2p);
}